// round 12
// baseline (speedup 1.0000x reference)
#include <cuda_runtime.h>
#include <cuda.h>
#include <cuda_fp16.h>
#include <cstdint>

#define NUM_OBS 100000
#define NUM_ACT 10
#define RD 64
#define MAXB 8192
#define BM 64
#define BN 128
#define THREADS 256
#define OFF_A 0
#define OFF_B 8192            // A: 64 rows x 128B = 8KB; B: 128 rows x 128B = 16KB
#define CSTRIDE 136           // fallback staged-C row stride in floats
#define SMEM_TMA (4 * 64 * 128 + 1024)        // 4 panels (8KB) + align pad
#define SMEM_FBK (BM * CSTRIDE * 4)           // 34816 B fallback staging

// Gathered fp16 operands (2 MB). Device globals = sanctioned scratch.
__device__ __half g_F16[MAXB * RD];
__device__ __half g_B16[MAXB * RD];

__device__ __forceinline__ int clampi(int v, int lo, int hi) {
    return v < lo ? lo : (v > hi ? hi : v);
}

__global__ void gather_kernel(
    const int* __restrict__ obs, const int* __restrict__ act,
    const int* __restrict__ fobs, const int* __restrict__ fact,
    const float* __restrict__ Wf, const float* __restrict__ Wb,
    int Btot)
{
    int i = blockIdx.x * 8 + (threadIdx.x >> 5);
    int lane = threadIdx.x & 31;
    if (i >= Btot) return;
    {
        int o = clampi(obs[i], 0, NUM_OBS - 1);
        int a = clampi(act[i], 0, NUM_ACT - 1);
        long long idx = (long long)o * NUM_ACT + a;
        float2 v = *(const float2*)(Wf + idx * RD + lane * 2);
        *(__half2*)(g_F16 + i * RD + lane * 2) = __floats2half2_rn(v.x, v.y);
    }
    {
        int o = clampi(fobs[i], 0, NUM_OBS - 1);
        int a = clampi(fact[i], 0, NUM_ACT - 1);
        long long idx = (long long)o * NUM_ACT + a;
        float2 v = *(const float2*)(Wb + idx * RD + lane * 2);
        *(__half2*)(g_B16 + i * RD + lane * 2) = __floats2half2_rn(v.x, v.y);
    }
}

__device__ __forceinline__ uint32_t smem_u32(const void* p) {
    uint32_t a;
    asm("{ .reg .u64 t; cvta.to.shared.u64 t, %1; cvt.u32.u64 %0, t; }"
        : "=r"(a) : "l"(p));
    return a;
}

__device__ __forceinline__ void cp_async16(uint32_t dst, const void* src) {
    asm volatile("cp.async.cg.shared.global [%0], [%1], 16;"
                 :: "r"(dst), "l"(src));
}

__device__ __forceinline__ void ldsm_x4(uint32_t& r0, uint32_t& r1,
                                        uint32_t& r2, uint32_t& r3,
                                        uint32_t addr)
{
    asm volatile(
        "ldmatrix.sync.aligned.m8n8.x4.shared.b16 {%0,%1,%2,%3}, [%4];"
        : "=r"(r0), "=r"(r1), "=r"(r2), "=r"(r3)
        : "r"(addr));
}

__device__ __forceinline__ void mma16816_f16(float* c, const uint32_t* a,
                                             const uint32_t* b)
{
    asm volatile(
        "mma.sync.aligned.m16n8k16.row.col.f32.f16.f16.f32 "
        "{%0,%1,%2,%3}, {%4,%5,%6,%7}, {%8,%9}, {%0,%1,%2,%3};"
        : "+f"(c[0]), "+f"(c[1]), "+f"(c[2]), "+f"(c[3])
        : "r"(a[0]), "r"(a[1]), "r"(a[2]), "r"(a[3]),
          "r"(b[0]), "r"(b[1]));
}

__device__ __forceinline__ void stg_cs_128(float* p, float4 v) {
    asm volatile("st.global.cs.v4.f32 [%0], {%1,%2,%3,%4};"
                 :: "l"(p), "f"(v.x), "f"(v.y), "f"(v.z), "f"(v.w)
                 : "memory");
}

// Shared mainloop: fills smem operands (base = 'sbase', raw ptr 'smem') and
// computes the 32x32 warp-tile accumulators. CTA tile 64x128, 8 warps.
__device__ __forceinline__ void fb_mainloop(
    uint8_t* smem, uint32_t sbase, int tileM, int tileN, int Btot,
    int tid, int wid, int lane, float c[2][4][4])
{
    {
        const uint4* srcA = (const uint4*)g_F16;
        const uint4* srcB = (const uint4*)g_B16;
#pragma unroll
        for (int it = 0; it < 2; it++) {           // A: 512 chunks
            int t = tid + it * THREADS;
            int r = t >> 3, ch = t & 7;
            uint32_t soff = OFF_A + r * 128 + ((ch ^ (r & 7)) << 4);
            int ga = tileM + r;
            if (ga < Btot) cp_async16(sbase + soff, srcA + ga * 8 + ch);
            else *(uint4*)(smem + soff) = make_uint4(0u, 0u, 0u, 0u);
        }
#pragma unroll
        for (int it = 0; it < 4; it++) {           // B: 1024 chunks
            int t = tid + it * THREADS;
            int r = t >> 3, ch = t & 7;
            uint32_t soff = OFF_B + r * 128 + ((ch ^ (r & 7)) << 4);
            int gb = tileN + r;
            if (gb < Btot) cp_async16(sbase + soff, srcB + gb * 8 + ch);
            else *(uint4*)(smem + soff) = make_uint4(0u, 0u, 0u, 0u);
        }
        asm volatile("cp.async.commit_group;");
        asm volatile("cp.async.wait_group 0;");
    }
    __syncthreads();

    const int m0w = (wid & 1) * 32;
    const int n0w = (wid >> 1) * 32;
    const int lr = lane & 7;
    const int lq = lane >> 3;
    const int row_add = lr + (lq & 1) * 8;
    const int kb_add = (lq >> 1) * 16;
    const int swz = lr << 4;

#pragma unroll
    for (int mf = 0; mf < 2; mf++)
#pragma unroll
        for (int nf = 0; nf < 4; nf++)
#pragma unroll
            for (int r = 0; r < 4; r++) c[mf][nf][r] = 0.0f;

#pragma unroll
    for (int ks = 0; ks < 4; ks++) {
        int kb = ks * 32;
        uint32_t a[2][4];
#pragma unroll
        for (int mf = 0; mf < 2; mf++) {
            int row = m0w + mf * 16 + row_add;
            uint32_t addr = sbase + OFF_A + row * 128 + ((kb + kb_add) ^ swz);
            ldsm_x4(a[mf][0], a[mf][1], a[mf][2], a[mf][3], addr);
        }
        uint32_t b[4][2];
#pragma unroll
        for (int nh = 0; nh < 2; nh++) {
            int row = n0w + nh * 16 + row_add;
            uint32_t addr = sbase + OFF_B + row * 128 + ((kb + kb_add) ^ swz);
            uint32_t r0, r1, r2, r3;
            ldsm_x4(r0, r1, r2, r3, addr);
            b[nh * 2 + 0][0] = r0;
            b[nh * 2 + 1][0] = r1;
            b[nh * 2 + 0][1] = r2;
            b[nh * 2 + 1][1] = r3;
        }
#pragma unroll
        for (int mf = 0; mf < 2; mf++)
#pragma unroll
            for (int nf = 0; nf < 4; nf++)
                mma16816_f16(c[mf][nf], a[mf], b[nf]);
    }
}

// ---- TMA-epilogue kernel: stage C into 4 SW128 panels, TMA bulk store ----
__global__ void __launch_bounds__(THREADS, 4) fb_gemm_tma(
    float* __restrict__ out, int Btot,
    const __grid_constant__ CUtensorMap tmap)
{
    extern __shared__ __align__(16) uint8_t smem_raw[];
    uint32_t sraw = smem_u32(smem_raw);
    uint32_t pad = (1024u - (sraw & 1023u)) & 1023u;
    uint8_t* smem = smem_raw + pad;
    uint32_t sbase = sraw + pad;

    const int tid = threadIdx.x;
    const int wid = tid >> 5, lane = tid & 31;
    const int tileM = blockIdx.y * BM;
    const int tileN = blockIdx.x * BN;

    float c[2][4][4];
    fb_mainloop(smem, sbase, tileM, tileN, Btot, tid, wid, lane, c);

    // ---- stage into panel (wid>>1): 64 rows x 128B, SW128 swizzle ----
    __syncthreads();  // operand smem dead; panels overlay it
    {
        uint8_t* pbase = smem + (wid >> 1) * 8192;
        const int m0w = (wid & 1) * 32;
        const int gid = lane >> 2, qid = lane & 3;
#pragma unroll
        for (int mf = 0; mf < 2; mf++) {
            int r0 = m0w + mf * 16 + gid;
            int r1 = r0 + 8;
#pragma unroll
            for (int nf = 0; nf < 4; nf++) {
                int b0 = nf * 32 + qid * 8;          // byte offset in 128B row
                int ch = b0 >> 4, bin = b0 & 15;
                uint32_t a0 = r0 * 128 + (((uint32_t)(ch ^ (r0 & 7))) << 4) + bin;
                uint32_t a1 = r1 * 128 + (((uint32_t)(ch ^ (r1 & 7))) << 4) + bin;
                *(float2*)(pbase + a0) = make_float2(c[mf][nf][0], c[mf][nf][1]);
                *(float2*)(pbase + a1) = make_float2(c[mf][nf][2], c[mf][nf][3]);
            }
        }
    }
    __syncthreads();

    if (tid == 0) {
        asm volatile("fence.proxy.async.shared::cta;" ::: "memory");
#pragma unroll
        for (int p = 0; p < 4; p++) {
            asm volatile(
                "cp.async.bulk.tensor.2d.global.shared::cta.tile.bulk_group "
                "[%0, {%1, %2}], [%3];"
                :: "l"(&tmap), "r"(tileN + p * 32), "r"(tileM),
                   "r"(sbase + p * 8192)
                : "memory");
        }
        asm volatile("cp.async.bulk.commit_group;" ::: "memory");
        asm volatile("cp.async.bulk.wait_group 0;" ::: "memory");
    }
}

// ---- fallback kernel: round-10 smem-staged STG epilogue ----
__global__ void __launch_bounds__(THREADS, 4) fb_gemm_fbk(
    float* __restrict__ out, int Btot)
{
    extern __shared__ __align__(16) uint8_t smem[];
    const uint32_t sbase = smem_u32(smem);
    const int tid = threadIdx.x;
    const int wid = tid >> 5, lane = tid & 31;
    const int tileM = blockIdx.y * BM;
    const int tileN = blockIdx.x * BN;

    float c[2][4][4];
    fb_mainloop((uint8_t*)smem, sbase, tileM, tileN, Btot, tid, wid, lane, c);

    __syncthreads();
    {
        float* cs = (float*)smem;
        const int m0w = (wid & 1) * 32;
        const int n0w = (wid >> 1) * 32;
        const int gid = lane >> 2, qid = lane & 3;
#pragma unroll
        for (int mf = 0; mf < 2; mf++) {
            int r0 = m0w + mf * 16 + gid;
#pragma unroll
            for (int nf = 0; nf < 4; nf++) {
                int col = n0w + nf * 8 + qid * 2;
                *(float2*)(cs + r0 * CSTRIDE + col) =
                    make_float2(c[mf][nf][0], c[mf][nf][1]);
                *(float2*)(cs + (r0 + 8) * CSTRIDE + col) =
                    make_float2(c[mf][nf][2], c[mf][nf][3]);
            }
        }
    }
    __syncthreads();
    {
        const float* cs = (const float*)smem;
#pragma unroll
        for (int i = 0; i < 8; i++) {
            int lrow = wid * 8 + i;
            int grow = tileM + lrow;
            if (grow >= Btot) continue;
            float4 v = *(const float4*)(cs + lrow * CSTRIDE + lane * 4);
            int gcol = tileN + lane * 4;
            if (tileN + BN <= Btot) {
                stg_cs_128(out + (size_t)grow * Btot + gcol, v);
            } else {
                float vv[4] = { v.x, v.y, v.z, v.w };
                for (int j = 0; j < 4; j++)
                    if (gcol + j < Btot)
                        out[(size_t)grow * Btot + gcol + j] = vv[j];
            }
        }
    }
}

typedef CUresult (*PFN_tmapEncode)(
    CUtensorMap*, CUtensorMapDataType, cuuint32_t, void*,
    const cuuint64_t*, const cuuint64_t*, const cuuint32_t*, const cuuint32_t*,
    CUtensorMapInterleave, CUtensorMapSwizzle, CUtensorMapL2promotion,
    CUtensorMapFloatOOBfill);

extern "C" void kernel_launch(void* const* d_in, const int* in_sizes, int n_in,
                              void* d_out, int out_size)
{
    const int* obs  = (const int*)d_in[0];
    const int* act  = (const int*)d_in[1];
    const int* fobs = (const int*)d_in[2];
    const int* fact = (const int*)d_in[3];
    const float* Wf = (const float*)d_in[4];
    const float* Wb = (const float*)d_in[5];
    float* out = (float*)d_out;
    int Btot = in_sizes[0];

    gather_kernel<<<(Btot + 7) / 8, 256>>>(obs, act, fobs, fact, Wf, Wb, Btot);

    dim3 grid((Btot + BN - 1) / BN, (Btot + BM - 1) / BM);

    // Try the TMA epilogue path: fetch cuTensorMapEncodeTiled via the runtime
    // (no -lcuda link), build a 2D SW128 f32 descriptor over the output.
    bool use_tma = (Btot % BM == 0) && (Btot % BN == 0);
    CUtensorMap tmap;
    if (use_tma) {
        void* fn = nullptr;
        cudaDriverEntryPointQueryResult qr =
            cudaDriverEntryPointSymbolNotFound;
#if CUDART_VERSION >= 12050
        cudaGetDriverEntryPointByVersion("cuTensorMapEncodeTiled", &fn, 12000,
                                         cudaEnableDefault, &qr);
#else
        cudaGetDriverEntryPoint("cuTensorMapEncodeTiled", &fn,
                                cudaEnableDefault, &qr);
#endif
        if (fn == nullptr || qr != cudaDriverEntryPointSuccess) {
            use_tma = false;
        } else {
            cuuint64_t dims[2] = { (cuuint64_t)Btot, (cuuint64_t)Btot };
            cuuint64_t strides[1] = { (cuuint64_t)Btot * sizeof(float) };
            cuuint32_t box[2] = { 32, 64 };   // 32 f32 = 128B (SW128 limit)
            cuuint32_t estr[2] = { 1, 1 };
            CUresult r = ((PFN_tmapEncode)fn)(
                &tmap, CU_TENSOR_MAP_DATA_TYPE_FLOAT32, 2, (void*)out,
                dims, strides, box, estr,
                CU_TENSOR_MAP_INTERLEAVE_NONE, CU_TENSOR_MAP_SWIZZLE_128B,
                CU_TENSOR_MAP_L2_PROMOTION_L2_128B,
                CU_TENSOR_MAP_FLOAT_OOB_FILL_NONE);
            if (r != CUDA_SUCCESS) use_tma = false;
        }
    }

    if (use_tma) {
        cudaFuncSetAttribute(fb_gemm_tma,
                             cudaFuncAttributeMaxDynamicSharedMemorySize,
                             SMEM_TMA);
        fb_gemm_tma<<<grid, THREADS, SMEM_TMA>>>(out, Btot, tmap);
    } else {
        cudaFuncSetAttribute(fb_gemm_fbk,
                             cudaFuncAttributeMaxDynamicSharedMemorySize,
                             SMEM_FBK);
        fb_gemm_fbk<<<grid, THREADS, SMEM_FBK>>>(out, Btot);
    }
}